// round 1
// baseline (speedup 1.0000x reference)
#include <cuda_runtime.h>
#include <math.h>
#include <stdint.h>

// ---------------- problem constants ----------------
#define BEAM   5
#define TOPK   5
#define VOCAB  128000
#define HIST   511
#define NUM_KV 16
#define HEADS  8
#define SEQ    2048
#define HDIM   128

#define KV_ROW_ELEMS  (HEADS*SEQ*HDIM)          // 2,097,152 floats per (kv,beam)
#define KV_ROW4       (KV_ROW_ELEMS/4)          // 524,288 float4
#define KV_ELEMS      (BEAM*KV_ROW_ELEMS)       // per kv tensor
#define KV_TOTAL      (NUM_KV*KV_ELEMS)         // 167,772,160

// output layout (floats), in reference tuple order
#define OFF_KV     0
#define OFF_SAVE   (KV_TOTAL)                        // 5*512 = 2560
#define OFF_RP     (OFF_SAVE + BEAM*(HIST+1))        // 640,000
#define OFF_PROB   (OFF_RP + BEAM*VOCAB)             // 5
#define OFF_TOK    (OFF_PROB + BEAM)                 // 5
#define OFF_MAXIDX (OFF_TOK + BEAM)                  // 1

// ---------------- device scratch (no allocations allowed) ----------------
__device__ float g_topk_val[BEAM*TOPK];
__device__ int   g_topk_idx[BEAM*TOPK];
__device__ int   g_beam_index[BEAM];
__device__ int   g_token[BEAM];

// ---------------- top-5 helpers ----------------
// Maintain descending list; ties broken by smaller index (jax.lax.top_k semantics).
__device__ __forceinline__ void top5_insert(float* v, int* ix, float val, int idx) {
    if (val < v[TOPK-1]) return;
    if (val == v[TOPK-1] && idx >= ix[TOPK-1]) return;
    int p = TOPK - 1;
    #pragma unroll
    for (int q = TOPK - 1; q > 0; q--) {
        if (val > v[q-1] || (val == v[q-1] && idx < ix[q-1])) {
            v[q] = v[q-1]; ix[q] = ix[q-1]; p = q - 1;
        } else {
            break;
        }
    }
    v[p] = val; ix[p] = idx;
}

__device__ __forceinline__ void warp_merge(float* v, int* ix, float& m, float& s) {
    #pragma unroll
    for (int off = 16; off > 0; off >>= 1) {
        float pv[TOPK]; int pi[TOPK];
        #pragma unroll
        for (int j = 0; j < TOPK; j++) {
            pv[j] = __shfl_down_sync(0xffffffffu, v[j],  off);
            pi[j] = __shfl_down_sync(0xffffffffu, ix[j], off);
        }
        float pm = __shfl_down_sync(0xffffffffu, m, off);
        float ps = __shfl_down_sync(0xffffffffu, s, off);
        #pragma unroll
        for (int j = 0; j < TOPK; j++) top5_insert(v, ix, pv[j], pi[j]);
        float nm = fmaxf(m, pm);
        s = s * expf(m - nm) + ps * expf(pm - nm);
        m = nm;
    }
}

// ---------------- kernel 1: per-beam logsumexp + top-5 of x = logits*rp ----------------
__global__ void __launch_bounds__(1024)
softmax_topk_kernel(const float* __restrict__ logits, const float* __restrict__ rpen) {
    const int b = blockIdx.x;
    const float* lg = logits + (size_t)b * VOCAB;
    const float* rp = rpen   + (size_t)b * VOCAB;

    float v[TOPK]; int ix[TOPK];
    #pragma unroll
    for (int j = 0; j < TOPK; j++) { v[j] = -INFINITY; ix[j] = 0x7FFFFFFF; }
    float m = -INFINITY, s = 0.0f;

    for (int j = threadIdx.x; j < VOCAB; j += blockDim.x) {
        float x = lg[j] * rp[j];
        if (x > m) { s = s * expf(m - x) + 1.0f; m = x; }
        else       { s += expf(x - m); }
        top5_insert(v, ix, x, j);
    }

    warp_merge(v, ix, m, s);

    __shared__ float sv[32][TOPK];
    __shared__ int   si[32][TOPK];
    __shared__ float sm[32], ss[32];
    const int warp = threadIdx.x >> 5;
    const int lane = threadIdx.x & 31;
    const int nwarps = blockDim.x >> 5;

    if (lane == 0) {
        #pragma unroll
        for (int j = 0; j < TOPK; j++) { sv[warp][j] = v[j]; si[warp][j] = ix[j]; }
        sm[warp] = m; ss[warp] = s;
    }
    __syncthreads();

    if (warp == 0) {
        if (lane < nwarps) {
            #pragma unroll
            for (int j = 0; j < TOPK; j++) { v[j] = sv[lane][j]; ix[j] = si[lane][j]; }
            m = sm[lane]; s = ss[lane];
        } else {
            #pragma unroll
            for (int j = 0; j < TOPK; j++) { v[j] = -INFINITY; ix[j] = 0x7FFFFFFF; }
            m = -INFINITY; s = 0.0f;
        }
        warp_merge(v, ix, m, s);
        if (lane == 0) {
            float lse = m + logf(s);
            #pragma unroll
            for (int j = 0; j < TOPK; j++) {
                g_topk_val[b*TOPK + j] = v[j] - lse;   // log_softmax value of top-j
                g_topk_idx[b*TOPK + j] = ix[j];
            }
        }
    }
}

// ---------------- kernel 2: combine 25 candidates -> beam_index/token ----------------
__global__ void combine_kernel(const float* __restrict__ prev_prob,
                               float* __restrict__ out_prob,
                               float* __restrict__ out_tok,
                               float* __restrict__ out_maxidx) {
    if (threadIdx.x != 0 || blockIdx.x != 0) return;
    float cur[BEAM*TOPK];
    #pragma unroll
    for (int i = 0; i < BEAM*TOPK; i++)
        cur[i] = g_topk_val[i] + prev_prob[i / TOPK];

    bool used[BEAM*TOPK];
    #pragma unroll
    for (int i = 0; i < BEAM*TOPK; i++) used[i] = false;

    for (int k = 0; k < BEAM; k++) {
        int best = -1; float bv = -INFINITY;
        for (int i = 0; i < BEAM*TOPK; i++) {
            if (!used[i] && cur[i] > bv) { bv = cur[i]; best = i; }  // strict > => lowest index on ties
        }
        used[best] = true;
        int bi  = best / TOPK;
        int tok = g_topk_idx[best];
        g_beam_index[k] = bi;
        g_token[k]      = tok;
        out_prob[k]     = bv;
        out_tok[k]      = (float)tok;
        if (k == 0) out_maxidx[0] = (float)tok;
    }
}

// ---------------- kernel 3: repeat-penalty gather + in-place penalty ----------------
__global__ void rp_kernel(const float* __restrict__ rpen,
                          const float* __restrict__ pen,
                          float* __restrict__ out) {
    int t = blockIdx.x * blockDim.x + threadIdx.x;
    if (t >= BEAM * VOCAB) return;
    int b = t / VOCAB;
    int vv = t - b * VOCAB;
    int bi = g_beam_index[b];
    float x = rpen[(size_t)bi * VOCAB + vv];
    if (vv == g_token[b]) x *= pen[0];
    out[t] = x;
}

// ---------------- kernel 4: save_id gather + append token ----------------
__global__ void save_kernel(const int* __restrict__ save_id, float* __restrict__ out) {
    int t = blockIdx.x * blockDim.x + threadIdx.x;
    if (t >= BEAM * (HIST + 1)) return;
    int b = t / (HIST + 1);
    int j = t - b * (HIST + 1);
    int bi = g_beam_index[b];
    out[t] = (j < HIST) ? (float)save_id[bi * HIST + j] : (float)g_token[b];
}

// ---------------- kernel 5: the big KV gather (HBM-bound) ----------------
struct KvPtrs { const float4* p[NUM_KV]; };

__global__ void __launch_bounds__(256)
kv_gather_kernel(KvPtrs kp, float4* __restrict__ out) {
    const int row = blockIdx.y;           // 0..79
    const int kv  = row / BEAM;
    const int b   = row - kv * BEAM;
    const int bi  = g_beam_index[b];

    const float4* __restrict__ src = kp.p[kv] + (size_t)bi * KV_ROW4;
    float4* __restrict__ dst = out + (size_t)kv * (BEAM * (size_t)KV_ROW4)
                                   + (size_t)b * KV_ROW4;

    const int stride = gridDim.x * blockDim.x;
    for (int j = blockIdx.x * blockDim.x + threadIdx.x; j < KV_ROW4; j += stride) {
        float4 val = __ldg(src + j);
        __stcs(dst + j, val);   // streaming store: output never re-read; keep L2 for src reuse
    }
}

// ---------------- launch ----------------
extern "C" void kernel_launch(void* const* d_in, const int* in_sizes, int n_in,
                              void* d_out, int out_size) {
    (void)in_sizes; (void)n_in; (void)out_size;

    const int*   save_id = (const int*)  d_in[16];
    const float* rpen    = (const float*)d_in[17];
    const float* prev    = (const float*)d_in[18];
    // d_in[19] = batch_indices (arange, unused — identity)
    const float* logits  = (const float*)d_in[20];
    const float* pen     = (const float*)d_in[21];
    float* out = (float*)d_out;

    // 1. per-beam log-softmax constants + top-5
    softmax_topk_kernel<<<BEAM, 1024>>>(logits, rpen);

    // 2. beam combine (writes beam_index/token scratch + small outputs)
    combine_kernel<<<1, 32>>>(prev, out + OFF_PROB, out + OFF_TOK, out + OFF_MAXIDX);

    // 3. repeat penalty gather (+ penalty at token)
    rp_kernel<<<(BEAM * VOCAB + 255) / 256, 256>>>(rpen, pen, out + OFF_RP);

    // 4. save_id gather + token append
    save_kernel<<<(BEAM * (HIST + 1) + 255) / 256, 256>>>(save_id, out + OFF_SAVE);

    // 5. KV gather — dominant, HBM-bound
    KvPtrs kp;
    for (int i = 0; i < NUM_KV; i++) kp.p[i] = (const float4*)d_in[i];
    dim3 grid(256, NUM_KV * BEAM);
    kv_gather_kernel<<<grid, 256>>>(kp, (float4*)out);
}

// round 2
// speedup vs baseline: 1.9676x; 1.9676x over previous
#include <cuda_runtime.h>
#include <math.h>
#include <stdint.h>

// ---------------- problem constants ----------------
#define BEAM   5
#define TOPK   5
#define VOCAB  128000
#define HIST   511
#define NUM_KV 16
#define HEADS  8
#define SEQ    2048
#define HDIM   128
#define CHUNKS 8                     // vocab chunks for softmax stage-1
#define CHUNK_V (VOCAB/CHUNKS)       // 16000

#define KV_ROW_ELEMS  (HEADS*SEQ*HDIM)          // 2,097,152 floats per (kv,beam)
#define KV_ROW4       (KV_ROW_ELEMS/4)          // 524,288 float4
#define KV_TOTAL      (NUM_KV*BEAM*KV_ROW_ELEMS)

// output layout (floats), in reference tuple order
#define OFF_SAVE   (KV_TOTAL)
#define OFF_RP     (OFF_SAVE + BEAM*(HIST+1))
#define OFF_PROB   (OFF_RP + BEAM*VOCAB)
#define OFF_TOK    (OFF_PROB + BEAM)
#define OFF_MAXIDX (OFF_TOK + BEAM)

// ---------------- device scratch ----------------
__device__ float g_pm[BEAM*CHUNKS];
__device__ float g_ps[BEAM*CHUNKS];
__device__ float g_pv[BEAM*CHUNKS*TOPK];
__device__ int   g_pi[BEAM*CHUNKS*TOPK];
__device__ int   g_beam_index[BEAM];
__device__ int   g_token[BEAM];

// ---------------- top-5 helpers (descending, ties -> lower index) ----------------
__device__ __forceinline__ void top5_insert(float* v, int* ix, float val, int idx) {
    if (val < v[TOPK-1]) return;
    if (val == v[TOPK-1] && idx >= ix[TOPK-1]) return;
    int p = TOPK - 1;
    #pragma unroll
    for (int q = TOPK - 1; q > 0; q--) {
        if (val > v[q-1] || (val == v[q-1] && idx < ix[q-1])) {
            v[q] = v[q-1]; ix[q] = ix[q-1]; p = q - 1;
        } else break;
    }
    v[p] = val; ix[p] = idx;
}

__device__ __forceinline__ void warp_merge(float* v, int* ix, float& m, float& s) {
    #pragma unroll
    for (int off = 16; off > 0; off >>= 1) {
        float pv[TOPK]; int pi[TOPK];
        #pragma unroll
        for (int j = 0; j < TOPK; j++) {
            pv[j] = __shfl_down_sync(0xffffffffu, v[j],  off);
            pi[j] = __shfl_down_sync(0xffffffffu, ix[j], off);
        }
        float pm = __shfl_down_sync(0xffffffffu, m, off);
        float ps = __shfl_down_sync(0xffffffffu, s, off);
        #pragma unroll
        for (int j = 0; j < TOPK; j++) top5_insert(v, ix, pv[j], pi[j]);
        float nm = fmaxf(m, pm);
        s = s * expf(m - nm) + ps * expf(pm - nm);
        m = nm;
    }
}

// ---------------- kernel 1: per-(beam,chunk) partial logsumexp + top-5 ----------------
__global__ void __launch_bounds__(1024)
softmax_topk_kernel(const float* __restrict__ logits, const float* __restrict__ rpen) {
    const int c = blockIdx.x;            // chunk
    const int b = blockIdx.y;            // beam
    const int base = c * CHUNK_V;
    const float* lg = logits + (size_t)b * VOCAB;
    const float* rp = rpen   + (size_t)b * VOCAB;

    float v[TOPK]; int ix[TOPK];
    #pragma unroll
    for (int j = 0; j < TOPK; j++) { v[j] = -INFINITY; ix[j] = 0x7FFFFFFF; }
    float m = -INFINITY, s = 0.0f;

    for (int j = base + threadIdx.x; j < base + CHUNK_V; j += blockDim.x) {
        float x = lg[j] * rp[j];
        if (x > m) { s = s * expf(m - x) + 1.0f; m = x; }
        else       { s += expf(x - m); }
        top5_insert(v, ix, x, j);
    }

    warp_merge(v, ix, m, s);

    __shared__ float sv[32][TOPK];
    __shared__ int   si[32][TOPK];
    __shared__ float sm[32], ss[32];
    const int warp = threadIdx.x >> 5;
    const int lane = threadIdx.x & 31;
    const int nwarps = blockDim.x >> 5;

    if (lane == 0) {
        #pragma unroll
        for (int j = 0; j < TOPK; j++) { sv[warp][j] = v[j]; si[warp][j] = ix[j]; }
        sm[warp] = m; ss[warp] = s;
    }
    __syncthreads();

    if (warp == 0) {
        if (lane < nwarps) {
            #pragma unroll
            for (int j = 0; j < TOPK; j++) { v[j] = sv[lane][j]; ix[j] = si[lane][j]; }
            m = sm[lane]; s = ss[lane];
        } else {
            #pragma unroll
            for (int j = 0; j < TOPK; j++) { v[j] = -INFINITY; ix[j] = 0x7FFFFFFF; }
            m = -INFINITY; s = 0.0f;
        }
        warp_merge(v, ix, m, s);
        if (lane == 0) {
            const int pc = b * CHUNKS + c;
            g_pm[pc] = m; g_ps[pc] = s;
            #pragma unroll
            for (int j = 0; j < TOPK; j++) {
                g_pv[pc*TOPK + j] = v[j];
                g_pi[pc*TOPK + j] = ix[j];
            }
        }
    }
}

// ---------------- kernel 2: merge partials + 25-candidate beam select ----------------
__global__ void combine_kernel(const float* __restrict__ prev_prob,
                               float* __restrict__ out_prob,
                               float* __restrict__ out_tok,
                               float* __restrict__ out_maxidx) {
    if (threadIdx.x != 0 || blockIdx.x != 0) return;

    float cur[BEAM*TOPK];
    int   ctok[BEAM*TOPK];

    for (int b = 0; b < BEAM; b++) {
        float v[TOPK]; int ix[TOPK];
        #pragma unroll
        for (int j = 0; j < TOPK; j++) { v[j] = -INFINITY; ix[j] = 0x7FFFFFFF; }
        float m = -INFINITY, s = 0.0f;
        for (int c = 0; c < CHUNKS; c++) {
            const int pc = b * CHUNKS + c;
            float pm = g_pm[pc], ps = g_ps[pc];
            float nm = fmaxf(m, pm);
            s = s * expf(m - nm) + ps * expf(pm - nm);
            m = nm;
            #pragma unroll
            for (int j = 0; j < TOPK; j++)
                top5_insert(v, ix, g_pv[pc*TOPK + j], g_pi[pc*TOPK + j]);
        }
        float lse = m + logf(s);
        float pp = prev_prob[b];
        #pragma unroll
        for (int j = 0; j < TOPK; j++) {
            cur[b*TOPK + j]  = v[j] - lse + pp;
            ctok[b*TOPK + j] = ix[j];
        }
    }

    bool used[BEAM*TOPK];
    #pragma unroll
    for (int i = 0; i < BEAM*TOPK; i++) used[i] = false;

    for (int k = 0; k < BEAM; k++) {
        int best = -1; float bv = -INFINITY;
        for (int i = 0; i < BEAM*TOPK; i++) {
            if (!used[i] && cur[i] > bv) { bv = cur[i]; best = i; }  // strict > => lowest index on ties
        }
        used[best] = true;
        int bi  = best / TOPK;
        int tok = ctok[best];
        g_beam_index[k] = bi;
        g_token[k]      = tok;
        out_prob[k]     = bv;
        out_tok[k]      = (float)tok;
        if (k == 0) out_maxidx[0] = (float)tok;
    }
}

// ---------------- kernel 3: fused gather (KV + repeat_penalty + save_id) ----------------
struct KvPtrs { const float4* p[NUM_KV]; };

#define KV_ROWS   (NUM_KV*BEAM)          // 80
#define RP_ROWS   3                      // ceil(160000/65536)
#define RP_F4     (BEAM*VOCAB/4)         // 160000
#define TPB       256
#define XBLK      256                    // 256*256 = 65536 threads per row

__global__ void __launch_bounds__(TPB)
gather_fused_kernel(KvPtrs kp,
                    const float* __restrict__ rpen,
                    const int*   __restrict__ save_id,
                    const float* __restrict__ pen,
                    float4* __restrict__ out) {
    const int row = blockIdx.y;

    if (row < KV_ROWS) {
        // ---- KV copy: 8 fully independent float4 loads per thread ----
        const int kv = row / BEAM;
        const int b  = row - kv * BEAM;
        const int bi = g_beam_index[b];

        const float4* __restrict__ src = kp.p[kv] + (size_t)bi * KV_ROW4;
        float4* __restrict__ dst = out + ((size_t)kv * BEAM + b) * KV_ROW4;

        const int j0 = blockIdx.x * TPB + threadIdx.x;   // 0..65535
        float4 vals[8];
        #pragma unroll
        for (int k = 0; k < 8; k++) vals[k] = __ldcg(src + j0 + k * 65536);
        #pragma unroll
        for (int k = 0; k < 8; k++) __stcs(dst + j0 + k * 65536, vals[k]);
        return;
    }

    if (row < KV_ROWS + RP_ROWS) {
        // ---- repeat_penalty gather (float4) + token penalty ----
        int t = (row - KV_ROWS) * 65536 + blockIdx.x * TPB + threadIdx.x;
        if (t >= RP_F4) return;
        int b  = t / (VOCAB/4);
        int v4 = t - b * (VOCAB/4);
        int bi = g_beam_index[b];
        float4 x = __ldcg((const float4*)rpen + (size_t)bi * (VOCAB/4) + v4);
        int tok = g_token[b];
        if ((tok >> 2) == v4) {
            float p = pen[0];
            ((float*)&x)[tok & 3] *= p;
        }
        float* o = (float*)out + OFF_RP;
        ((float4*)o)[t] = x;
        return;
    }

    // ---- save_id gather + token append ----
    int t = blockIdx.x * TPB + threadIdx.x;
    if (t >= BEAM * (HIST + 1)) return;
    int b = t / (HIST + 1);
    int j = t - b * (HIST + 1);
    int bi = g_beam_index[b];
    float* o = (float*)out + OFF_SAVE;
    o[t] = (j < HIST) ? (float)save_id[bi * HIST + j] : (float)g_token[b];
}

// ---------------- launch ----------------
extern "C" void kernel_launch(void* const* d_in, const int* in_sizes, int n_in,
                              void* d_out, int out_size) {
    (void)in_sizes; (void)n_in; (void)out_size;

    const int*   save_id = (const int*)  d_in[16];
    const float* rpen    = (const float*)d_in[17];
    const float* prev    = (const float*)d_in[18];
    // d_in[19] = batch_indices (arange, identity — unused)
    const float* logits  = (const float*)d_in[20];
    const float* pen     = (const float*)d_in[21];
    float* out = (float*)d_out;

    softmax_topk_kernel<<<dim3(CHUNKS, BEAM), 1024>>>(logits, rpen);

    combine_kernel<<<1, 32>>>(prev, out + OFF_PROB, out + OFF_TOK, out + OFF_MAXIDX);

    KvPtrs kp;
    for (int i = 0; i < NUM_KV; i++) kp.p[i] = (const float4*)d_in[i];
    dim3 grid(XBLK, KV_ROWS + RP_ROWS + 1);
    gather_fused_kernel<<<grid, TPB>>>(kp, rpen, save_id, pen, (float4*)out);
}